// round 16
// baseline (speedup 1.0000x reference)
#include <cuda_runtime.h>
#include <cuda_fp16.h>
#include <stdint.h>

// ---------------- problem constants ----------------
#define N_USERS 100000
#define N_ITEMS 50000
#define NNODES  150000           // N_USERS + N_ITEMS
#define EMB_DIM 64
#define NNZ     6400000
#define BATCH   4096
#define N_LAYERS 3

#define SLOT    128               // fixed bucket per row (max degree ~80)
#define SCAT_T  (NNZ / 8)         // 8 edges per thread (2x int4)
#define INIT_T  (NNODES * EMB_DIM / 4)    // float4 init work items

// val in [0, 0.05): 14-bit fixed point. q = rn(val*327680), v = q/327680
#define VAL_SCALE   327680.0f
#define VAL_INV     (1.0f / 327680.0f)

// ---------------- device scratch (static, allocation-free) ----------------
__device__ int          g_fill[NNODES];            // per-row edge count
__device__ unsigned int g_edges[NNODES * SLOT];    // (dst<<14)|q14(val), bucketed
__device__ __half       g_xh[3][NNODES * EMB_DIM]; // x0, x1, x2

__device__ __forceinline__ __half2 u2h2(unsigned int u) {
    return *reinterpret_cast<__half2*>(&u);
}
__device__ __forceinline__ unsigned int h22u(__half2 h) {
    return *reinterpret_cast<unsigned int*>(&h);
}

// ---------------- cleanup first: zero fill counters -------------------------
__global__ void k_cleanup() {
    int i = blockIdx.x * blockDim.x + threadIdx.x;
    if (i < NNODES) g_fill[i] = 0;
}

// ---------------- single-pass build: bucket scatter + x0 fp16 init ----------
__device__ __forceinline__ unsigned int pack_edge(int d, float v) {
    unsigned int q = __float2uint_rn(v * VAL_SCALE);
    if (q > 16383u) q = 16383u;
    return ((unsigned int)d << 14) | q;
}

__global__ void k_build(const int4* __restrict__ src4,
                        const int4* __restrict__ dst4,
                        const float4* __restrict__ val4,
                        const float4* __restrict__ user_emb,
                        const float4* __restrict__ item_emb) {
    int t = blockIdx.x * blockDim.x + threadIdx.x;
    if (t < SCAT_T) {
        // 8 edges: two int4/float4 groups -> 8 concurrent atomic chains
        int4   s0 = src4[2 * t],     s1 = src4[2 * t + 1];
        int4   d0 = dst4[2 * t],     d1 = dst4[2 * t + 1];
        float4 v0 = val4[2 * t],     v1 = val4[2 * t + 1];
        int p;
        p = atomicAdd(&g_fill[s0.x], 1); g_edges[s0.x * SLOT + p] = pack_edge(d0.x, v0.x);
        p = atomicAdd(&g_fill[s0.y], 1); g_edges[s0.y * SLOT + p] = pack_edge(d0.y, v0.y);
        p = atomicAdd(&g_fill[s0.z], 1); g_edges[s0.z * SLOT + p] = pack_edge(d0.z, v0.z);
        p = atomicAdd(&g_fill[s0.w], 1); g_edges[s0.w * SLOT + p] = pack_edge(d0.w, v0.w);
        p = atomicAdd(&g_fill[s1.x], 1); g_edges[s1.x * SLOT + p] = pack_edge(d1.x, v1.x);
        p = atomicAdd(&g_fill[s1.y], 1); g_edges[s1.y * SLOT + p] = pack_edge(d1.y, v1.y);
        p = atomicAdd(&g_fill[s1.z], 1); g_edges[s1.z * SLOT + p] = pack_edge(d1.z, v1.z);
        p = atomicAdd(&g_fill[s1.w], 1); g_edges[s1.w * SLOT + p] = pack_edge(d1.w, v1.w);
    } else {
        int i = t - SCAT_T;
        if (i < INIT_T) {
            const int us = N_USERS * EMB_DIM / 4;
            float4 v = (i < us) ? user_emb[i] : item_emb[i - us];
            __half2 a = __floats2half2_rn(v.x, v.y);
            __half2 b = __floats2half2_rn(v.z, v.w);
            uint2 o;
            o.x = h22u(a);
            o.y = h22u(b);
            ((uint2*)&g_xh[0][0])[i] = o;
        }
    }
}

// ---------------- shared row-SpMM core (warp-collective) -------------------
// HFMA2 accumulation in fp16, flushed to fp32 every 32 edges (per chunk).
// X-row gathers use __ldcg (L2-only; 19MB stream would only thrash L1).
// On return, EVERY lane holds the 8 reduced sums for column block (lane&7).
__device__ __forceinline__ void spmm_row(const uint4* __restrict__ Xv,
                                         int row, int lane, int col, int grp,
                                         float* a) {
    int beg = row * SLOT;
    int end = beg + g_fill[row];

    float a0 = 0.f, a1 = 0.f, a2 = 0.f, a3 = 0.f;
    float a4 = 0.f, a5 = 0.f, a6 = 0.f, a7 = 0.f;
    const __half2 hz = __floats2half2_rn(0.f, 0.f);

#define FLUSH()                                                              \
    {                                                                        \
        float2 f;                                                            \
        f = __half22float2(c0); a0 += f.x; a1 += f.y;                        \
        f = __half22float2(c1); a2 += f.x; a3 += f.y;                        \
        f = __half22float2(c2); a4 += f.x; a5 += f.y;                        \
        f = __half22float2(c3); a6 += f.x; a7 += f.y;                        \
    }

    int e = beg;
    for (; e + 32 <= end; e += 32) {
        unsigned int pk = g_edges[e + lane];
        int d = (int)(pk >> 14);
        float vf = (float)(pk & 16383u) * VAL_INV;
        unsigned int vh = h22u(__float2half2_rn(vf));   // (v, v) as fp16x2

        __half2 c0 = hz, c1 = hz, c2 = hz, c3 = hz;
#pragma unroll
        for (int s = 0; s < 8; s++) {
            int jidx = s * 4 + grp;
            int          dj = __shfl_sync(0xffffffffu, d,  jidx);
            unsigned int vj = __shfl_sync(0xffffffffu, vh, jidx);
            __half2 vv = u2h2(vj);
            uint4 q = __ldcg(&Xv[dj * 8 + col]);
            c0 = __hfma2(vv, u2h2(q.x), c0);
            c1 = __hfma2(vv, u2h2(q.y), c1);
            c2 = __hfma2(vv, u2h2(q.z), c2);
            c3 = __hfma2(vv, u2h2(q.w), c3);
        }
        FLUSH()
    }
    int rem = end - e;
    if (rem > 0) {
        unsigned int pk = (lane < rem) ? g_edges[e + lane] : 0u;
        int d = (int)(pk >> 14);
        float vf = (float)(pk & 16383u) * VAL_INV;
        unsigned int vh = h22u(__float2half2_rn(vf));
        int nsteps = (rem + 3) >> 2;
        __half2 c0 = hz, c1 = hz, c2 = hz, c3 = hz;
        for (int s = 0; s < nsteps; s++) {
            int jidx = s * 4 + grp;
            int          dj = __shfl_sync(0xffffffffu, d,  jidx);
            unsigned int vj = __shfl_sync(0xffffffffu, vh, jidx);
            if (jidx >= rem) { dj = 0; vj = 0u; }
            __half2 vv = u2h2(vj);
            uint4 q = __ldcg(&Xv[dj * 8 + col]);
            c0 = __hfma2(vv, u2h2(q.x), c0);
            c1 = __hfma2(vv, u2h2(q.y), c1);
            c2 = __hfma2(vv, u2h2(q.z), c2);
            c3 = __hfma2(vv, u2h2(q.w), c3);
        }
        FLUSH()
    }
#undef FLUSH

#pragma unroll
    for (int off = 8; off <= 16; off <<= 1) {
        a0 += __shfl_xor_sync(0xffffffffu, a0, off);
        a1 += __shfl_xor_sync(0xffffffffu, a1, off);
        a2 += __shfl_xor_sync(0xffffffffu, a2, off);
        a3 += __shfl_xor_sync(0xffffffffu, a3, off);
        a4 += __shfl_xor_sync(0xffffffffu, a4, off);
        a5 += __shfl_xor_sync(0xffffffffu, a5, off);
        a6 += __shfl_xor_sync(0xffffffffu, a6, off);
        a7 += __shfl_xor_sync(0xffffffffu, a7, off);
    }
    a[0] = a0; a[1] = a1; a[2] = a2; a[3] = a3;
    a[4] = a4; a[5] = a5; a[6] = a6; a[7] = a7;
}

// add fp16 row (8 halves at column block col) into a[0..7]
__device__ __forceinline__ void add_h_row(const uint4* __restrict__ Xv,
                                          int row, int col, float* a) {
    uint4 q = __ldcg(&Xv[row * 8 + col]);
    float2 f;
    f = __half22float2(u2h2(q.x)); a[0] += f.x; a[1] += f.y;
    f = __half22float2(u2h2(q.y)); a[2] += f.x; a[3] += f.y;
    f = __half22float2(u2h2(q.z)); a[4] += f.x; a[5] += f.y;
    f = __half22float2(u2h2(q.w)); a[6] += f.x; a[7] += f.y;
}

// ---------------- dense SpMM layers 1..2: warp per row ---------------------
// __launch_bounds__(256, 7): cap regs at 36 -> 56 resident warps/SM (87.5%).
__global__ void __launch_bounds__(256, 7) k_spmm(int layer) {
    const int row  = (blockIdx.x * blockDim.x + threadIdx.x) >> 5;
    const int lane = threadIdx.x & 31;
    if (row >= NNODES) return;

    const uint4* __restrict__ Xv = (const uint4*)&g_xh[layer - 1][0];
    uint4* __restrict__ Xout     = (uint4*)&g_xh[layer][0];

    float a[8];
    spmm_row(Xv, row, lane, lane & 7, lane >> 3, a);

    if (lane < 8) {
        __half2 o0 = __floats2half2_rn(a[0], a[1]);
        __half2 o1 = __floats2half2_rn(a[2], a[3]);
        __half2 o2 = __floats2half2_rn(a[4], a[5]);
        __half2 o3 = __floats2half2_rn(a[6], a[7]);
        uint4 o;
        o.x = h22u(o0);
        o.y = h22u(o1);
        o.z = h22u(o2);
        o.w = h22u(o3);
        Xout[row * 8 + lane] = o;
    }
}

// ---------------- fused layer-3 + score: one warp per pair -----------------
// x3 is computed on the fly ONLY at queried nodes (8192 of 150000 rows).
// acc = x0(fp32 inputs) + x1 + x2 + x3; score = dot(acc_u, acc_i)/16.
__global__ void __launch_bounds__(256, 6) k_spmm3_score(
        const int* __restrict__ users,
        const int* __restrict__ items,
        const float4* __restrict__ user_emb,
        const float4* __restrict__ item_emb,
        float* __restrict__ out) {
    const int pair = (blockIdx.x * blockDim.x + threadIdx.x) >> 5;
    const int lane = threadIdx.x & 31;
    if (pair >= BATCH) return;
    const int col = lane & 7;
    const int grp = lane >> 3;

    int u    = users[pair];
    int it   = items[pair];
    int irow = N_USERS + it;

    const uint4* __restrict__ X1 = (const uint4*)&g_xh[1][0];
    const uint4* __restrict__ X2 = (const uint4*)&g_xh[2][0];

    // x3 rows via gather over x2
    float au[8], ai[8];
    spmm_row(X2, u,    lane, col, grp, au);
    spmm_row(X2, irow, lane, col, grp, ai);

    // + x1 + x2 (fp16)
    add_h_row(X1, u,    col, au);
    add_h_row(X2, u,    col, au);
    add_h_row(X1, irow, col, ai);
    add_h_row(X2, irow, col, ai);

    // + x0 (fp32 inputs; 16 float4 per row)
    float4 ua = __ldg(&user_emb[u * 16 + col * 2]);
    float4 ub = __ldg(&user_emb[u * 16 + col * 2 + 1]);
    au[0] += ua.x; au[1] += ua.y; au[2] += ua.z; au[3] += ua.w;
    au[4] += ub.x; au[5] += ub.y; au[6] += ub.z; au[7] += ub.w;
    float4 ia = __ldg(&item_emb[it * 16 + col * 2]);
    float4 ib = __ldg(&item_emb[it * 16 + col * 2 + 1]);
    ai[0] += ia.x; ai[1] += ia.y; ai[2] += ia.z; ai[3] += ia.w;
    ai[4] += ib.x; ai[5] += ib.y; ai[6] += ib.z; ai[7] += ib.w;

    // dot over this lane's 8 columns, then reduce across the 8 col blocks
    float p = 0.f;
#pragma unroll
    for (int k = 0; k < 8; k++) p = fmaf(au[k], ai[k], p);
#pragma unroll
    for (int off = 1; off < 8; off <<= 1)
        p += __shfl_xor_sync(0xffffffffu, p, off);

    if (lane == 0) out[pair] = p * (1.0f / 16.0f);
}

// ---------------- launch ----------------
extern "C" void kernel_launch(void* const* d_in, const int* in_sizes, int n_in,
                              void* d_out, int out_size) {
    const float* user_emb  = (const float*)d_in[0];
    const float* item_emb  = (const float*)d_in[1];
    const float* graph_val = (const float*)d_in[2];
    const int*   graph_src = (const int*)d_in[3];
    const int*   graph_dst = (const int*)d_in[4];
    const int*   users     = (const int*)d_in[5];
    const int*   items     = (const int*)d_in[6];
    float* out = (float*)d_out;

    // launch 0: zero the per-row fill counters
    k_cleanup<<<(NNODES + 255) / 256, 256>>>();

    // launch 1: single-pass bucket scatter (8 edges/thread) + x0->fp16 init
    k_build<<<(SCAT_T + INIT_T + 255) / 256, 256>>>(
        (const int4*)graph_src, (const int4*)graph_dst,
        (const float4*)graph_val,
        (const float4*)user_emb, (const float4*)item_emb);

    // launches 2-3: dense propagation layers 1 and 2 (warp per row)
    const int spmm_blocks = (NNODES + 7) / 8;
    for (int l = 1; l <= 2; l++)
        k_spmm<<<spmm_blocks, 256>>>(l);

    // launch 4: fused sparse layer-3 + score (only queried rows)
    k_spmm3_score<<<(BATCH + 7) / 8, 256>>>(users, items,
                                            (const float4*)user_emb,
                                            (const float4*)item_emb, out);
}

// round 17
// speedup vs baseline: 1.2543x; 1.2543x over previous
#include <cuda_runtime.h>
#include <cuda_fp16.h>
#include <stdint.h>

// ---------------- problem constants ----------------
#define N_USERS 100000
#define N_ITEMS 50000
#define NNODES  150000           // N_USERS + N_ITEMS
#define EMB_DIM 64
#define NNZ     6400000
#define BATCH   4096
#define N_LAYERS 3

#define SLOT    128               // fixed bucket per row (max degree ~80)
#define SCAT_T  (NNZ / 8)         // 8 edges per thread (2x int4)
#define INIT_T  (NNODES * EMB_DIM / 4)    // float4 init work items

// val in [0, 0.05): 14-bit fixed point. q = rn(val*327680), v = q/327680
#define VAL_SCALE   327680.0f
#define VAL_INV     (1.0f / 327680.0f)

// ---------------- device scratch (static, allocation-free) ----------------
__device__ int          g_fill[NNODES];            // per-row edge count
__device__ unsigned int g_edges[NNODES * SLOT];    // (dst<<14)|q14(val), bucketed
__device__ __half       g_xh[3][NNODES * EMB_DIM]; // x0, x1, x2

__device__ __forceinline__ __half2 u2h2(unsigned int u) {
    return *reinterpret_cast<__half2*>(&u);
}
__device__ __forceinline__ unsigned int h22u(__half2 h) {
    return *reinterpret_cast<unsigned int*>(&h);
}

// ---------------- cleanup first: zero fill counters -------------------------
__global__ void k_cleanup() {
    int i = blockIdx.x * blockDim.x + threadIdx.x;
    if (i < NNODES) g_fill[i] = 0;
}

// ---------------- single-pass build: bucket scatter + x0 fp16 init ----------
__device__ __forceinline__ unsigned int pack_edge(int d, float v) {
    unsigned int q = __float2uint_rn(v * VAL_SCALE);
    if (q > 16383u) q = 16383u;
    return ((unsigned int)d << 14) | q;
}

__global__ void k_build(const int4* __restrict__ src4,
                        const int4* __restrict__ dst4,
                        const float4* __restrict__ val4,
                        const float4* __restrict__ user_emb,
                        const float4* __restrict__ item_emb) {
    int t = blockIdx.x * blockDim.x + threadIdx.x;
    if (t < SCAT_T) {
        // 8 edges: two int4/float4 groups -> 8 concurrent atomic chains
        int4   s0 = src4[2 * t],     s1 = src4[2 * t + 1];
        int4   d0 = dst4[2 * t],     d1 = dst4[2 * t + 1];
        float4 v0 = val4[2 * t],     v1 = val4[2 * t + 1];
        int p;
        p = atomicAdd(&g_fill[s0.x], 1); g_edges[s0.x * SLOT + p] = pack_edge(d0.x, v0.x);
        p = atomicAdd(&g_fill[s0.y], 1); g_edges[s0.y * SLOT + p] = pack_edge(d0.y, v0.y);
        p = atomicAdd(&g_fill[s0.z], 1); g_edges[s0.z * SLOT + p] = pack_edge(d0.z, v0.z);
        p = atomicAdd(&g_fill[s0.w], 1); g_edges[s0.w * SLOT + p] = pack_edge(d0.w, v0.w);
        p = atomicAdd(&g_fill[s1.x], 1); g_edges[s1.x * SLOT + p] = pack_edge(d1.x, v1.x);
        p = atomicAdd(&g_fill[s1.y], 1); g_edges[s1.y * SLOT + p] = pack_edge(d1.y, v1.y);
        p = atomicAdd(&g_fill[s1.z], 1); g_edges[s1.z * SLOT + p] = pack_edge(d1.z, v1.z);
        p = atomicAdd(&g_fill[s1.w], 1); g_edges[s1.w * SLOT + p] = pack_edge(d1.w, v1.w);
    } else {
        int i = t - SCAT_T;
        if (i < INIT_T) {
            const int us = N_USERS * EMB_DIM / 4;
            float4 v = (i < us) ? user_emb[i] : item_emb[i - us];
            __half2 a = __floats2half2_rn(v.x, v.y);
            __half2 b = __floats2half2_rn(v.z, v.w);
            uint2 o;
            o.x = h22u(a);
            o.y = h22u(b);
            ((uint2*)&g_xh[0][0])[i] = o;
        }
    }
}

// ---------------- shared row-SpMM core (warp-collective) -------------------
// HFMA2 accumulation in fp16, flushed to fp32 every 32 edges (per chunk).
// X-row gathers use __ldcg (L2-only; 19MB stream would only thrash L1).
// On return, EVERY lane holds the 8 reduced sums for column block (lane&7).
__device__ __forceinline__ void spmm_row(const uint4* __restrict__ Xv,
                                         int row, int lane, int col, int grp,
                                         float* a) {
    int beg = row * SLOT;
    int end = beg + g_fill[row];

    float a0 = 0.f, a1 = 0.f, a2 = 0.f, a3 = 0.f;
    float a4 = 0.f, a5 = 0.f, a6 = 0.f, a7 = 0.f;
    const __half2 hz = __floats2half2_rn(0.f, 0.f);

#define FLUSH()                                                              \
    {                                                                        \
        float2 f;                                                            \
        f = __half22float2(c0); a0 += f.x; a1 += f.y;                        \
        f = __half22float2(c1); a2 += f.x; a3 += f.y;                        \
        f = __half22float2(c2); a4 += f.x; a5 += f.y;                        \
        f = __half22float2(c3); a6 += f.x; a7 += f.y;                        \
    }

    int e = beg;
    for (; e + 32 <= end; e += 32) {
        unsigned int pk = g_edges[e + lane];
        int d = (int)(pk >> 14);
        float vf = (float)(pk & 16383u) * VAL_INV;
        unsigned int vh = h22u(__float2half2_rn(vf));   // (v, v) as fp16x2

        __half2 c0 = hz, c1 = hz, c2 = hz, c3 = hz;
#pragma unroll
        for (int s = 0; s < 8; s++) {
            int jidx = s * 4 + grp;
            int          dj = __shfl_sync(0xffffffffu, d,  jidx);
            unsigned int vj = __shfl_sync(0xffffffffu, vh, jidx);
            __half2 vv = u2h2(vj);
            uint4 q = __ldcg(&Xv[dj * 8 + col]);
            c0 = __hfma2(vv, u2h2(q.x), c0);
            c1 = __hfma2(vv, u2h2(q.y), c1);
            c2 = __hfma2(vv, u2h2(q.z), c2);
            c3 = __hfma2(vv, u2h2(q.w), c3);
        }
        FLUSH()
    }
    int rem = end - e;
    if (rem > 0) {
        unsigned int pk = (lane < rem) ? g_edges[e + lane] : 0u;
        int d = (int)(pk >> 14);
        float vf = (float)(pk & 16383u) * VAL_INV;
        unsigned int vh = h22u(__float2half2_rn(vf));
        int nsteps = (rem + 3) >> 2;
        __half2 c0 = hz, c1 = hz, c2 = hz, c3 = hz;
        for (int s = 0; s < nsteps; s++) {
            int jidx = s * 4 + grp;
            int          dj = __shfl_sync(0xffffffffu, d,  jidx);
            unsigned int vj = __shfl_sync(0xffffffffu, vh, jidx);
            if (jidx >= rem) { dj = 0; vj = 0u; }
            __half2 vv = u2h2(vj);
            uint4 q = __ldcg(&Xv[dj * 8 + col]);
            c0 = __hfma2(vv, u2h2(q.x), c0);
            c1 = __hfma2(vv, u2h2(q.y), c1);
            c2 = __hfma2(vv, u2h2(q.z), c2);
            c3 = __hfma2(vv, u2h2(q.w), c3);
        }
        FLUSH()
    }
#undef FLUSH

#pragma unroll
    for (int off = 8; off <= 16; off <<= 1) {
        a0 += __shfl_xor_sync(0xffffffffu, a0, off);
        a1 += __shfl_xor_sync(0xffffffffu, a1, off);
        a2 += __shfl_xor_sync(0xffffffffu, a2, off);
        a3 += __shfl_xor_sync(0xffffffffu, a3, off);
        a4 += __shfl_xor_sync(0xffffffffu, a4, off);
        a5 += __shfl_xor_sync(0xffffffffu, a5, off);
        a6 += __shfl_xor_sync(0xffffffffu, a6, off);
        a7 += __shfl_xor_sync(0xffffffffu, a7, off);
    }
    a[0] = a0; a[1] = a1; a[2] = a2; a[3] = a3;
    a[4] = a4; a[5] = a5; a[6] = a6; a[7] = a7;
}

// add fp16 row (8 halves at column block col) into a[0..7]
__device__ __forceinline__ void add_h_row(const uint4* __restrict__ Xv,
                                          int row, int col, float* a) {
    uint4 q = __ldcg(&Xv[row * 8 + col]);
    float2 f;
    f = __half22float2(u2h2(q.x)); a[0] += f.x; a[1] += f.y;
    f = __half22float2(u2h2(q.y)); a[2] += f.x; a[3] += f.y;
    f = __half22float2(u2h2(q.z)); a[4] += f.x; a[5] += f.y;
    f = __half22float2(u2h2(q.w)); a[6] += f.x; a[7] += f.y;
}

// ---------------- dense SpMM layers 1..2: warp per row ---------------------
// __launch_bounds__(256, 6): 40 regs (no spill), 48 resident warps/SM.
__global__ void __launch_bounds__(256, 6) k_spmm(int layer) {
    const int row  = (blockIdx.x * blockDim.x + threadIdx.x) >> 5;
    const int lane = threadIdx.x & 31;
    if (row >= NNODES) return;

    const uint4* __restrict__ Xv = (const uint4*)&g_xh[layer - 1][0];
    uint4* __restrict__ Xout     = (uint4*)&g_xh[layer][0];

    float a[8];
    spmm_row(Xv, row, lane, lane & 7, lane >> 3, a);

    if (lane < 8) {
        __half2 o0 = __floats2half2_rn(a[0], a[1]);
        __half2 o1 = __floats2half2_rn(a[2], a[3]);
        __half2 o2 = __floats2half2_rn(a[4], a[5]);
        __half2 o3 = __floats2half2_rn(a[6], a[7]);
        uint4 o;
        o.x = h22u(o0);
        o.y = h22u(o1);
        o.z = h22u(o2);
        o.w = h22u(o3);
        Xout[row * 8 + lane] = o;
    }
}

// ---------------- fused layer-3 + score: one warp per pair -----------------
// x3 is computed on the fly ONLY at queried nodes (8192 of 150000 rows).
// acc = x0(fp32 inputs) + x1 + x2 + x3; score = dot(acc_u, acc_i)/16.
__global__ void __launch_bounds__(256) k_spmm3_score(
        const int* __restrict__ users,
        const int* __restrict__ items,
        const float4* __restrict__ user_emb,
        const float4* __restrict__ item_emb,
        float* __restrict__ out) {
    const int pair = (blockIdx.x * blockDim.x + threadIdx.x) >> 5;
    const int lane = threadIdx.x & 31;
    if (pair >= BATCH) return;
    const int col = lane & 7;
    const int grp = lane >> 3;

    int u    = users[pair];
    int it   = items[pair];
    int irow = N_USERS + it;

    const uint4* __restrict__ X1 = (const uint4*)&g_xh[1][0];
    const uint4* __restrict__ X2 = (const uint4*)&g_xh[2][0];

    // x3 rows via gather over x2
    float au[8], ai[8];
    spmm_row(X2, u,    lane, col, grp, au);
    spmm_row(X2, irow, lane, col, grp, ai);

    // + x1 + x2 (fp16)
    add_h_row(X1, u,    col, au);
    add_h_row(X2, u,    col, au);
    add_h_row(X1, irow, col, ai);
    add_h_row(X2, irow, col, ai);

    // + x0 (fp32 inputs; 16 float4 per row)
    float4 ua = __ldg(&user_emb[u * 16 + col * 2]);
    float4 ub = __ldg(&user_emb[u * 16 + col * 2 + 1]);
    au[0] += ua.x; au[1] += ua.y; au[2] += ua.z; au[3] += ua.w;
    au[4] += ub.x; au[5] += ub.y; au[6] += ub.z; au[7] += ub.w;
    float4 ia = __ldg(&item_emb[it * 16 + col * 2]);
    float4 ib = __ldg(&item_emb[it * 16 + col * 2 + 1]);
    ai[0] += ia.x; ai[1] += ia.y; ai[2] += ia.z; ai[3] += ia.w;
    ai[4] += ib.x; ai[5] += ib.y; ai[6] += ib.z; ai[7] += ib.w;

    // dot over this lane's 8 columns, then reduce across the 8 col blocks
    float p = 0.f;
#pragma unroll
    for (int k = 0; k < 8; k++) p = fmaf(au[k], ai[k], p);
#pragma unroll
    for (int off = 1; off < 8; off <<= 1)
        p += __shfl_xor_sync(0xffffffffu, p, off);

    if (lane == 0) out[pair] = p * (1.0f / 16.0f);
}

// ---------------- launch ----------------
extern "C" void kernel_launch(void* const* d_in, const int* in_sizes, int n_in,
                              void* d_out, int out_size) {
    const float* user_emb  = (const float*)d_in[0];
    const float* item_emb  = (const float*)d_in[1];
    const float* graph_val = (const float*)d_in[2];
    const int*   graph_src = (const int*)d_in[3];
    const int*   graph_dst = (const int*)d_in[4];
    const int*   users     = (const int*)d_in[5];
    const int*   items     = (const int*)d_in[6];
    float* out = (float*)d_out;

    // launch 0: zero the per-row fill counters
    k_cleanup<<<(NNODES + 255) / 256, 256>>>();

    // launch 1: single-pass bucket scatter (8 edges/thread) + x0->fp16 init
    k_build<<<(SCAT_T + INIT_T + 255) / 256, 256>>>(
        (const int4*)graph_src, (const int4*)graph_dst,
        (const float4*)graph_val,
        (const float4*)user_emb, (const float4*)item_emb);

    // launches 2-3: dense propagation layers 1 and 2 (warp per row)
    const int spmm_blocks = (NNODES + 7) / 8;
    for (int l = 1; l <= 2; l++)
        k_spmm<<<spmm_blocks, 256>>>(l);

    // launch 4: fused sparse layer-3 + score (only queried rows)
    k_spmm3_score<<<(BATCH + 7) / 8, 256>>>(users, items,
                                            (const float4*)user_emb,
                                            (const float4*)item_emb, out);
}